// round 6
// baseline (speedup 1.0000x reference)
#include <cuda_runtime.h>
#include <cuda_bf16.h>
#include <cstdint>

#define C_DIM   768
#define QKV_DIM 3072
#define BATCH   4
#define SEQ     1024
#define HEADS   12
#define HD      64
#define M_ROWS  (BATCH*SEQ)   // 4096

typedef __nv_bfloat16 bf16;

// -------- limb scratch (allocation-free: device globals) --------
__device__ bf16 g_x_hi[M_ROWS*C_DIM],     g_x_lo[M_ROWS*C_DIM];
__device__ bf16 g_y_hi[M_ROWS*C_DIM],     g_y_lo[M_ROWS*C_DIM];
__device__ bf16 g_wqkv_hi[QKV_DIM*C_DIM], g_wqkv_lo[QKV_DIM*C_DIM];
__device__ bf16 g_wproj_hi[C_DIM*C_DIM],  g_wproj_lo[C_DIM*C_DIM];
__device__ bf16 g_qkvx_hi[M_ROWS*QKV_DIM], g_qkvx_lo[M_ROWS*QKV_DIM];
__device__ bf16 g_qkvy_hi[M_ROWS*QKV_DIM], g_qkvy_lo[M_ROWS*QKV_DIM];
__device__ bf16 g_attx_hi[M_ROWS*C_DIM],  g_attx_lo[M_ROWS*C_DIM];
__device__ bf16 g_atty_hi[M_ROWS*C_DIM],  g_atty_lo[M_ROWS*C_DIM];

// ============================================================
// helpers
// ============================================================
__device__ __forceinline__ uint32_t smem_u32(const void* p) {
    uint32_t a;
    asm("{ .reg .u64 t; cvta.to.shared.u64 t, %1; cvt.u32.u64 %0, t; }"
        : "=r"(a) : "l"(p));
    return a;
}

__device__ __forceinline__ void ldsm_x4(uint32_t addr, uint32_t& r0, uint32_t& r1,
                                        uint32_t& r2, uint32_t& r3) {
    asm volatile("ldmatrix.sync.aligned.m8n8.x4.shared.b16 {%0,%1,%2,%3}, [%4];"
                 : "=r"(r0), "=r"(r1), "=r"(r2), "=r"(r3) : "r"(addr));
}

__device__ __forceinline__ void ldsm_x4_t(uint32_t addr, uint32_t& r0, uint32_t& r1,
                                          uint32_t& r2, uint32_t& r3) {
    asm volatile("ldmatrix.sync.aligned.m8n8.x4.trans.shared.b16 {%0,%1,%2,%3}, [%4];"
                 : "=r"(r0), "=r"(r1), "=r"(r2), "=r"(r3) : "r"(addr));
}

__device__ __forceinline__ void mma_bf16(float* c, const uint32_t* a,
                                         uint32_t b0, uint32_t b1) {
    asm volatile(
        "mma.sync.aligned.m16n8k16.row.col.f32.bf16.bf16.f32 "
        "{%0,%1,%2,%3}, {%4,%5,%6,%7}, {%8,%9}, {%0,%1,%2,%3};"
        : "+f"(c[0]), "+f"(c[1]), "+f"(c[2]), "+f"(c[3])
        : "r"(a[0]), "r"(a[1]), "r"(a[2]), "r"(a[3]), "r"(b0), "r"(b1));
}

__device__ __forceinline__ void cp_async16(uint32_t saddr, const void* gptr) {
    asm volatile("cp.async.cg.shared.global [%0], [%1], 16;"
                 :: "r"(saddr), "l"(gptr));
}
__device__ __forceinline__ void cp_commit() {
    asm volatile("cp.async.commit_group;" ::: "memory");
}
__device__ __forceinline__ void cp_wait0() {
    asm volatile("cp.async.wait_group 0;" ::: "memory");
}
__device__ __forceinline__ void cp_wait1() {
    asm volatile("cp.async.wait_group 1;" ::: "memory");
}

__device__ __forceinline__ uint32_t pack_bf2(bf16 a, bf16 b) {
    return ((uint32_t)__bfloat16_as_ushort(b) << 16) | (uint32_t)__bfloat16_as_ushort(a);
}

// split fp32 float4 -> hi/lo bf16 limb pairs (2x uint2)
__device__ __forceinline__ void split4(float4 v, uint2& hi, uint2& lo) {
    bf16 h0 = __float2bfloat16_rn(v.x);
    bf16 h1 = __float2bfloat16_rn(v.y);
    bf16 h2 = __float2bfloat16_rn(v.z);
    bf16 h3 = __float2bfloat16_rn(v.w);
    bf16 l0 = __float2bfloat16_rn(v.x - __bfloat162float(h0));
    bf16 l1 = __float2bfloat16_rn(v.y - __bfloat162float(h1));
    bf16 l2 = __float2bfloat16_rn(v.z - __bfloat162float(h2));
    bf16 l3 = __float2bfloat16_rn(v.w - __bfloat162float(h3));
    hi.x = pack_bf2(h0, h1); hi.y = pack_bf2(h2, h3);
    lo.x = pack_bf2(l0, l1); lo.y = pack_bf2(l2, l3);
}

// split a scalar pair -> packed hi / lo uint32
__device__ __forceinline__ void split2_pack(float a, float b, uint32_t& hi, uint32_t& lo) {
    bf16 h0 = __float2bfloat16_rn(a);
    bf16 h1 = __float2bfloat16_rn(b);
    hi = pack_bf2(h0, h1);
    lo = pack_bf2(__float2bfloat16_rn(a - __bfloat162float(h0)),
                  __float2bfloat16_rn(b - __bfloat162float(h1)));
}

// ============================================================
// fp32 -> limb split kernel (memory-bound pre-pass)
// ============================================================
__global__ __launch_bounds__(256) void split_kernel(
    const float* __restrict__ src, bf16* __restrict__ hi,
    bf16* __restrict__ lo, int n4)
{
    int i = blockIdx.x * 256 + threadIdx.x;
    if (i < n4) {
        float4 v = ((const float4*)src)[i];
        uint2 h, l;
        split4(v, h, l);
        ((uint2*)hi)[i] = h;
        ((uint2*)lo)[i] = l;
    }
}

// ============================================================
// split-bf16 mma.sync GEMM, limbs in, cp.async double-buffered,
// 2 CTAs/SM. Output: fp32 (+bias) or limb pair.
// ============================================================
#define LDH 40
#define ARR (128 * LDH)           // 5120 halves per limb array
#define STGH (4 * ARR)            // halves per stage
#define GEMM_SMEM (2 * STGH * 2)  // 81920 bytes

__global__ __launch_bounds__(256, 2) void gemm_mma(
    const bf16* __restrict__ Ah0, const bf16* __restrict__ Al0,
    const bf16* __restrict__ Ah1, const bf16* __restrict__ Al1,
    const bf16* __restrict__ Bh,  const bf16* __restrict__ Bl,
    const float* __restrict__ bias,
    float* __restrict__ Cf0, float* __restrict__ Cf1,
    bf16* __restrict__ Ch0, bf16* __restrict__ Cl0,
    bf16* __restrict__ Ch1, bf16* __restrict__ Cl1,
    int M, int N, int K)
{
    extern __shared__ __align__(16) bf16 sh[];
    const int tid  = threadIdx.x;
    const int wid  = tid >> 5;
    const int lane = tid & 31;
    const int m0 = blockIdx.y * 128, n0 = blockIdx.x * 128;
    const int wm = (wid >> 2) * 64;
    const int wn = (wid & 3) * 32;
    const int S  = K / 32;

    const bf16* A_h = blockIdx.z ? Ah1 : Ah0;
    const bf16* A_l = blockIdx.z ? Al1 : Al0;

    const uint32_t sbase = smem_u32(sh);
    const int a_row = (wm + (lane & 15)) * LDH + ((lane >> 4) << 3);
    const int b_row = (wn + ((lane >> 4) << 3) + (lane & 7)) * LDH + (((lane >> 3) & 1) << 3);

    float acc[4][4][4];
#pragma unroll
    for (int i = 0; i < 4; i++)
#pragma unroll
        for (int j = 0; j < 4; j++)
#pragma unroll
            for (int r = 0; r < 4; r++) acc[i][j][r] = 0.f;

    auto issue_stage = [&](int s, int buf) {
        const int kb = s * 32;
        const int so = buf * STGH;
#pragma unroll
        for (int a = 0; a < 4; a++) {
            const bf16* src = (a == 0) ? A_h : (a == 1) ? A_l : (a == 2) ? Bh : Bl;
            const int rb = (a < 2) ? m0 : n0;
#pragma unroll
            for (int j = 0; j < 2; j++) {
                int cid = tid + j * 256;       // 0..511
                int row = cid & 127;
                int c   = cid >> 7;            // 0..3
                cp_async16(sbase + (uint32_t)(so + a * ARR + row * LDH + c * 8) * 2u,
                           src + (size_t)(rb + row) * K + kb + c * 8);
            }
        }
    };

    issue_stage(0, 0);
    cp_commit();

    for (int s = 0; s < S; s++) {
        if (s + 1 < S) { issue_stage(s + 1, (s + 1) & 1); cp_commit(); cp_wait1(); }
        else           { cp_wait0(); }
        __syncthreads();

        const uint32_t stg = sbase + (uint32_t)((s & 1) * STGH) * 2u;
#pragma unroll
        for (int ks = 0; ks < 2; ks++) {
            const int kofs = ks * 16;
            uint32_t ah[4][4], al[4][4];
#pragma unroll
            for (int mt = 0; mt < 4; mt++) {
                uint32_t ra = stg + (uint32_t)(a_row + mt * 16 * LDH + kofs) * 2u;
                ldsm_x4(ra,            ah[mt][0], ah[mt][1], ah[mt][2], ah[mt][3]);
                ldsm_x4(ra + ARR * 2u, al[mt][0], al[mt][1], al[mt][2], al[mt][3]);
            }
            uint32_t bh[4][2], bl[4][2];
#pragma unroll
            for (int p = 0; p < 2; p++) {
                uint32_t rb = stg + (uint32_t)(b_row + p * 16 * LDH + kofs) * 2u + 2u * ARR * 2u;
                ldsm_x4(rb,            bh[p*2][0], bh[p*2][1], bh[p*2+1][0], bh[p*2+1][1]);
                ldsm_x4(rb + ARR * 2u, bl[p*2][0], bl[p*2][1], bl[p*2+1][0], bl[p*2+1][1]);
            }
#pragma unroll
            for (int mt = 0; mt < 4; mt++)
#pragma unroll
                for (int nt = 0; nt < 4; nt++)
                    mma_bf16(acc[mt][nt], ah[mt], bh[nt][0], bh[nt][1]);
#pragma unroll
            for (int mt = 0; mt < 4; mt++)
#pragma unroll
                for (int nt = 0; nt < 4; nt++)
                    mma_bf16(acc[mt][nt], ah[mt], bl[nt][0], bl[nt][1]);
#pragma unroll
            for (int mt = 0; mt < 4; mt++)
#pragma unroll
                for (int nt = 0; nt < 4; nt++)
                    mma_bf16(acc[mt][nt], al[mt], bh[nt][0], bh[nt][1]);
        }
        if (s + 1 < S) __syncthreads();
    }

    if (Cf0) {
        float* C = blockIdx.z ? Cf1 : Cf0;
#pragma unroll
        for (int mt = 0; mt < 4; mt++) {
            int row0 = m0 + wm + mt * 16 + (lane >> 2);
#pragma unroll
            for (int nt = 0; nt < 4; nt++) {
                int col = n0 + wn + nt * 8 + (lane & 3) * 2;
                float b0 = 0.f, b1 = 0.f;
                if (bias) { b0 = __ldg(bias + col); b1 = __ldg(bias + col + 1); }
                float2 v0 = make_float2(acc[mt][nt][0] + b0, acc[mt][nt][1] + b1);
                float2 v1 = make_float2(acc[mt][nt][2] + b0, acc[mt][nt][3] + b1);
                *(float2*)(C + (size_t)row0 * N + col)       = v0;
                *(float2*)(C + (size_t)(row0 + 8) * N + col) = v1;
            }
        }
    } else {
        bf16* Ch = blockIdx.z ? Ch1 : Ch0;
        bf16* Cl = blockIdx.z ? Cl1 : Cl0;
#pragma unroll
        for (int mt = 0; mt < 4; mt++) {
            int row0 = m0 + wm + mt * 16 + (lane >> 2);
#pragma unroll
            for (int nt = 0; nt < 4; nt++) {
                int col = n0 + wn + nt * 8 + (lane & 3) * 2;
                uint32_t h, l;
                split2_pack(acc[mt][nt][0], acc[mt][nt][1], h, l);
                *(uint32_t*)(Ch + (size_t)row0 * N + col) = h;
                *(uint32_t*)(Cl + (size_t)row0 * N + col) = l;
                split2_pack(acc[mt][nt][2], acc[mt][nt][3], h, l);
                *(uint32_t*)(Ch + (size_t)(row0 + 8) * N + col) = h;
                *(uint32_t*)(Cl + (size_t)(row0 + 8) * N + col) = l;
            }
        }
    }
}

// ============================================================
// Dual-softmax flash attention on mma.sync, limb inputs,
// cp.async double-buffered K/V, ldmatrix.trans for V.
// ============================================================
#define AQS 72                            // halves per row (64 + 8 pad)
#define OKV  (4*128*AQS)                  // KV buffers start (halves)
#define KVH  (4*64*AQS)                   // halves per KV buffer
#define ATT_SMEM ((OKV + 2*KVH) * 2)      // 147456 bytes

__global__ __launch_bounds__(256, 1) void attention_mma()
{
    extern __shared__ __align__(16) bf16 sh[];
    const uint32_t sb = smem_u32(sh);
    const int tid  = threadIdx.x;
    const int wid  = tid >> 5;
    const int lane = tid & 31;
    const int wm   = wid * 16;

    const int b    = blockIdx.z;
    const int h    = blockIdx.y >> 1;
    const int pair = blockIdx.y & 1;
    const int q0   = blockIdx.x * 128;
    const int hoff = h * HD;

    const size_t bofs = (size_t)b * SEQ * QKV_DIM;
    const bf16 *q1h, *q1l, *q2h, *q2l, *kh, *kl;
    bf16 *outh, *outl;
    if (pair == 0) {
        q1h = g_qkvx_hi + bofs + C_DIM + hoff;   q1l = g_qkvx_lo + bofs + C_DIM + hoff;
        q2h = g_qkvy_hi + bofs + hoff;           q2l = g_qkvy_lo + bofs + hoff;
        kh  = g_qkvx_hi + bofs + 2*C_DIM + hoff; kl  = g_qkvx_lo + bofs + 2*C_DIM + hoff;
        outh = g_attx_hi; outl = g_attx_lo;
    } else {
        q1h = g_qkvy_hi + bofs + C_DIM + hoff;   q1l = g_qkvy_lo + bofs + C_DIM + hoff;
        q2h = g_qkvx_hi + bofs + hoff;           q2l = g_qkvx_lo + bofs + hoff;
        kh  = g_qkvy_hi + bofs + 2*C_DIM + hoff; kl  = g_qkvy_lo + bofs + 2*C_DIM + hoff;
        outh = g_atty_hi; outl = g_atty_lo;
    }
    const bf16* vh_src = g_qkvx_hi + bofs + 3*C_DIM + hoff;  // vy = vx
    const bf16* vl_src = g_qkvx_lo + bofs + 3*C_DIM + hoff;

    // ---- issue Q limbs (one-time) ----
    {
        const bf16* qsrc[4] = { q1h, q1l, q2h, q2l };
#pragma unroll
        for (int a = 0; a < 4; a++) {
#pragma unroll
            for (int j = 0; j < 4; j++) {
                int cid = tid + j * 256;     // 0..1023
                int row = cid & 127;
                int c   = cid >> 7;          // 0..7
                cp_async16(sb + (uint32_t)(a * 128 * AQS + row * AQS + c * 8) * 2u,
                           qsrc[a] + (size_t)(q0 + row) * QKV_DIM + c * 8);
            }
        }
    }

    auto issue_kv = [&](int kt, int buf) {
        const int j0 = kt * 64;
        const int nb = OKV + buf * KVH;
        const bf16* src[4] = { kh, kl, vh_src, vl_src };
#pragma unroll
        for (int a = 0; a < 4; a++) {
#pragma unroll
            for (int j = 0; j < 2; j++) {
                int cid = tid + j * 256;     // 0..511
                int row = cid & 63;
                int c   = cid >> 6;          // 0..7
                cp_async16(sb + (uint32_t)(nb + a * 64 * AQS + row * AQS + c * 8) * 2u,
                           src[a] + (size_t)(j0 + row) * QKV_DIM + c * 8);
            }
        }
    };

    issue_kv(0, 0);
    cp_commit();   // group: Q + tile 0

    // accumulators / softmax state
    float o1[8][4], o2[8][4];
#pragma unroll
    for (int d = 0; d < 8; d++)
#pragma unroll
        for (int r = 0; r < 4; r++) { o1[d][r] = 0.f; o2[d][r] = 0.f; }
    float m1lo = -1e30f, m1hi = -1e30f, l1lo = 0.f, l1hi = 0.f;
    float m2lo = -1e30f, m2hi = -1e30f, l2lo = 0.f, l2hi = 0.f;

    const uint32_t a_base = (uint32_t)((wm + (lane & 15)) * AQS + ((lane >> 4) << 3)) * 2u;
    const uint32_t b_base = (uint32_t)((((lane >> 4) << 3) + (lane & 7)) * AQS
                                       + (((lane >> 3) & 1) << 3)) * 2u;
    const uint32_t v_base = (uint32_t)(((((lane >> 3) & 1) << 3) + (lane & 7)) * AQS
                                       + ((lane >> 4) << 3)) * 2u;

    for (int kt = 0; kt < 16; kt++) {
        const uint32_t kvb = (uint32_t)(OKV + (kt & 1) * KVH) * 2u;

        if (kt < 15) { issue_kv(kt + 1, (kt + 1) & 1); cp_commit(); cp_wait1(); }
        else         { cp_wait0(); }
        __syncthreads();

        // ---- S = Q K^T (both streams, 3 limbs, stream-interleaved) ----
        float s1[8][4], s2[8][4];
#pragma unroll
        for (int n = 0; n < 8; n++)
#pragma unroll
            for (int r = 0; r < 4; r++) { s1[n][r] = 0.f; s2[n][r] = 0.f; }

#pragma unroll
        for (int ks = 0; ks < 4; ks++) {
            const uint32_t kofs = (uint32_t)(ks * 16) * 2u;
            uint32_t a1h[4], a1l[4], a2h[4], a2l[4];
            ldsm_x4(sb + a_base + kofs,                               a1h[0], a1h[1], a1h[2], a1h[3]);
            ldsm_x4(sb + (uint32_t)(128*AQS)*2u   + a_base + kofs,    a1l[0], a1l[1], a1l[2], a1l[3]);
            ldsm_x4(sb + (uint32_t)(2*128*AQS)*2u + a_base + kofs,    a2h[0], a2h[1], a2h[2], a2h[3]);
            ldsm_x4(sb + (uint32_t)(3*128*AQS)*2u + a_base + kofs,    a2l[0], a2l[1], a2l[2], a2l[3]);
#pragma unroll
            for (int jt = 0; jt < 4; jt++) {
                uint32_t rb = sb + kvb + b_base + (uint32_t)(jt * 16 * AQS) * 2u + kofs;
                uint32_t bh[2][2], bl[2][2];
                ldsm_x4(rb,                          bh[0][0], bh[0][1], bh[1][0], bh[1][1]);
                ldsm_x4(rb + (uint32_t)(64*AQS)*2u,  bl[0][0], bl[0][1], bl[1][0], bl[1][1]);
#pragma unroll
                for (int q = 0; q < 2; q++) {
                    int nt = jt * 2 + q;
                    mma_bf16(s1[nt], a1h, bh[q][0], bh[q][1]);
                    mma_bf16(s2[nt], a2h, bh[q][0], bh[q][1]);
                    mma_bf16(s1[nt], a1h, bl[q][0], bl[q][1]);
                    mma_bf16(s2[nt], a2h, bl[q][0], bl[q][1]);
                    mma_bf16(s1[nt], a1l, bh[q][0], bh[q][1]);
                    mma_bf16(s2[nt], a2l, bh[q][0], bh[q][1]);
                }
            }
        }

        // scale: S1 *= hd^-0.5, S2 *= -hd^-0.5 (exact power-of-two)
#pragma unroll
        for (int n = 0; n < 8; n++)
#pragma unroll
            for (int r = 0; r < 4; r++) {
                s1[n][r] *=  0.125f;
                s2[n][r] *= -0.125f;
            }

        // ---- online softmax (per stream), produce P limb A-fragments ----
        uint32_t p1h[8][2], p1l[8][2], p2h[8][2], p2l[8][2];
        {
            float mxlo = -1e30f, mxhi = -1e30f;
#pragma unroll
            for (int n = 0; n < 8; n++) {
                mxlo = fmaxf(mxlo, fmaxf(s1[n][0], s1[n][1]));
                mxhi = fmaxf(mxhi, fmaxf(s1[n][2], s1[n][3]));
            }
            mxlo = fmaxf(mxlo, __shfl_xor_sync(0xffffffffu, mxlo, 1));
            mxlo = fmaxf(mxlo, __shfl_xor_sync(0xffffffffu, mxlo, 2));
            mxhi = fmaxf(mxhi, __shfl_xor_sync(0xffffffffu, mxhi, 1));
            mxhi = fmaxf(mxhi, __shfl_xor_sync(0xffffffffu, mxhi, 2));
            float mnlo = fmaxf(m1lo, mxlo), mnhi = fmaxf(m1hi, mxhi);
            float clo = __expf(m1lo - mnlo), chi = __expf(m1hi - mnhi);
            m1lo = mnlo; m1hi = mnhi;
            float sl = 0.f, shh = 0.f;
#pragma unroll
            for (int n = 0; n < 8; n++) {
                float p0 = __expf(s1[n][0] - mnlo);
                float p1 = __expf(s1[n][1] - mnlo);
                float p2 = __expf(s1[n][2] - mnhi);
                float p3 = __expf(s1[n][3] - mnhi);
                sl += p0 + p1; shh += p2 + p3;
                uint32_t hh, ll;
                split2_pack(p0, p1, hh, ll);
                p1h[n][0] = hh; p1l[n][0] = ll;
                split2_pack(p2, p3, hh, ll);
                p1h[n][1] = hh; p1l[n][1] = ll;
            }
            sl  += __shfl_xor_sync(0xffffffffu, sl, 1);
            sl  += __shfl_xor_sync(0xffffffffu, sl, 2);
            shh += __shfl_xor_sync(0xffffffffu, shh, 1);
            shh += __shfl_xor_sync(0xffffffffu, shh, 2);
            l1lo = l1lo * clo + sl; l1hi = l1hi * chi + shh;
#pragma unroll
            for (int d = 0; d < 8; d++) {
                o1[d][0] *= clo; o1[d][1] *= clo;
                o1[d][2] *= chi; o1[d][3] *= chi;
            }
        }
        {
            float mxlo = -1e30f, mxhi = -1e30f;
#pragma unroll
            for (int n = 0; n < 8; n++) {
                mxlo = fmaxf(mxlo, fmaxf(s2[n][0], s2[n][1]));
                mxhi = fmaxf(mxhi, fmaxf(s2[n][2], s2[n][3]));
            }
            mxlo = fmaxf(mxlo, __shfl_xor_sync(0xffffffffu, mxlo, 1));
            mxlo = fmaxf(mxlo, __shfl_xor_sync(0xffffffffu, mxlo, 2));
            mxhi = fmaxf(mxhi, __shfl_xor_sync(0xffffffffu, mxhi, 1));
            mxhi = fmaxf(mxhi, __shfl_xor_sync(0xffffffffu, mxhi, 2));
            float mnlo = fmaxf(m2lo, mxlo), mnhi = fmaxf(m2hi, mxhi);
            float clo = __expf(m2lo - mnlo), chi = __expf(m2hi - mnhi);
            m2lo = mnlo; m2hi = mnhi;
            float sl = 0.f, shh = 0.f;
#pragma unroll
            for (int n = 0; n < 8; n++) {
                float p0 = __expf(s2[n][0] - mnlo);
                float p1 = __expf(s2[n][1] - mnlo);
                float p2 = __expf(s2[n][2] - mnhi);
                float p3 = __expf(s2[n][3] - mnhi);
                sl += p0 + p1; shh += p2 + p3;
                uint32_t hh, ll;
                split2_pack(p0, p1, hh, ll);
                p2h[n][0] = hh; p2l[n][0] = ll;
                split2_pack(p2, p3, hh, ll);
                p2h[n][1] = hh; p2l[n][1] = ll;
            }
            sl  += __shfl_xor_sync(0xffffffffu, sl, 1);
            sl  += __shfl_xor_sync(0xffffffffu, sl, 2);
            shh += __shfl_xor_sync(0xffffffffu, shh, 1);
            shh += __shfl_xor_sync(0xffffffffu, shh, 2);
            l2lo = l2lo * clo + sl; l2hi = l2hi * chi + shh;
#pragma unroll
            for (int d = 0; d < 8; d++) {
                o2[d][0] *= clo; o2[d][1] *= clo;
                o2[d][2] *= chi; o2[d][3] *= chi;
            }
        }

        // ---- O += P V (V row-major [j][d], ldmatrix.trans) ----
        const uint32_t vb = kvb + (uint32_t)(2 * 64 * AQS) * 2u;
#pragma unroll
        for (int ks = 0; ks < 4; ks++) {
            uint32_t a1hf[4] = { p1h[2*ks][0], p1h[2*ks][1], p1h[2*ks+1][0], p1h[2*ks+1][1] };
            uint32_t a1lf[4] = { p1l[2*ks][0], p1l[2*ks][1], p1l[2*ks+1][0], p1l[2*ks+1][1] };
            uint32_t a2hf[4] = { p2h[2*ks][0], p2h[2*ks][1], p2h[2*ks+1][0], p2h[2*ks+1][1] };
            uint32_t a2lf[4] = { p2l[2*ks][0], p2l[2*ks][1], p2l[2*ks+1][0], p2l[2*ks+1][1] };
            const uint32_t krow = (uint32_t)(ks * 16 * AQS) * 2u;
#pragma unroll
            for (int dt2 = 0; dt2 < 4; dt2++) {
                uint32_t ra = sb + vb + v_base + krow + (uint32_t)(dt2 * 16) * 2u;
                uint32_t vh[2][2], vl[2][2];
                ldsm_x4_t(ra,                          vh[0][0], vh[0][1], vh[1][0], vh[1][1]);
                ldsm_x4_t(ra + (uint32_t)(64*AQS)*2u,  vl[0][0], vl[0][1], vl[1][0], vl[1][1]);
#pragma unroll
                for (int q = 0; q < 2; q++) {
                    int dt = dt2 * 2 + q;
                    mma_bf16(o1[dt], a1hf, vh[q][0], vh[q][1]);
                    mma_bf16(o2[dt], a2hf, vh[q][0], vh[q][1]);
                    mma_bf16(o1[dt], a1hf, vl[q][0], vl[q][1]);
                    mma_bf16(o2[dt], a2hf, vl[q][0], vl[q][1]);
                    mma_bf16(o1[dt], a1lf, vh[q][0], vh[q][1]);
                    mma_bf16(o2[dt], a2lf, vh[q][0], vh[q][1]);
                }
            }
        }

        if (kt < 15) __syncthreads();
    }

    // ---- epilogue: out = O1/l1 + O2/l2, emit limbs ----
    const float i1lo = 1.f / l1lo, i1hi = 1.f / l1hi;
    const float i2lo = 1.f / l2lo, i2hi = 1.f / l2hi;
    const size_t obase = (size_t)b * SEQ * C_DIM;
    const int r0 = q0 + wm + (lane >> 2);
    const int cb = hoff + (lane & 3) * 2;
#pragma unroll
    for (int dt = 0; dt < 8; dt++) {
        int col = cb + dt * 8;
        float v0 = o1[dt][0] * i1lo + o2[dt][0] * i2lo;
        float v1 = o1[dt][1] * i1lo + o2[dt][1] * i2lo;
        float v2 = o1[dt][2] * i1hi + o2[dt][2] * i2hi;
        float v3 = o1[dt][3] * i1hi + o2[dt][3] * i2hi;
        uint32_t hh, ll;
        split2_pack(v0, v1, hh, ll);
        *(uint32_t*)(outh + obase + (size_t)r0 * C_DIM + col) = hh;
        *(uint32_t*)(outl + obase + (size_t)r0 * C_DIM + col) = ll;
        split2_pack(v2, v3, hh, ll);
        *(uint32_t*)(outh + obase + (size_t)(r0 + 8) * C_DIM + col) = hh;
        *(uint32_t*)(outl + obase + (size_t)(r0 + 8) * C_DIM + col) = ll;
    }
}

// ============================================================
extern "C" void kernel_launch(void* const* d_in, const int* in_sizes, int n_in,
                              void* d_out, int out_size)
{
    const float* x      = (const float*)d_in[0];
    const float* y      = (const float*)d_in[1];
    const float* w_qkv  = (const float*)d_in[2];
    const float* w_proj = (const float*)d_in[3];
    const float* b_proj = (const float*)d_in[4];
    float* out = (float*)d_out;

    bf16 *xh, *xl, *yh, *yl, *wqh, *wql, *wph, *wpl;
    bf16 *qxh, *qxl, *qyh, *qyl, *axh, *axl, *ayh, *ayl;
    cudaGetSymbolAddress((void**)&xh,  g_x_hi);     cudaGetSymbolAddress((void**)&xl,  g_x_lo);
    cudaGetSymbolAddress((void**)&yh,  g_y_hi);     cudaGetSymbolAddress((void**)&yl,  g_y_lo);
    cudaGetSymbolAddress((void**)&wqh, g_wqkv_hi);  cudaGetSymbolAddress((void**)&wql, g_wqkv_lo);
    cudaGetSymbolAddress((void**)&wph, g_wproj_hi); cudaGetSymbolAddress((void**)&wpl, g_wproj_lo);
    cudaGetSymbolAddress((void**)&qxh, g_qkvx_hi);  cudaGetSymbolAddress((void**)&qxl, g_qkvx_lo);
    cudaGetSymbolAddress((void**)&qyh, g_qkvy_hi);  cudaGetSymbolAddress((void**)&qyl, g_qkvy_lo);
    cudaGetSymbolAddress((void**)&axh, g_attx_hi);  cudaGetSymbolAddress((void**)&axl, g_attx_lo);
    cudaGetSymbolAddress((void**)&ayh, g_atty_hi);  cudaGetSymbolAddress((void**)&ayl, g_atty_lo);

    cudaFuncSetAttribute(gemm_mma,
                         cudaFuncAttributeMaxDynamicSharedMemorySize, GEMM_SMEM);
    cudaFuncSetAttribute(attention_mma,
                         cudaFuncAttributeMaxDynamicSharedMemorySize, ATT_SMEM);

    // 0) fp32 -> limb pre-splits
    split_kernel<<<(M_ROWS*C_DIM/4 + 255)/256, 256>>>(x, xh, xl, M_ROWS*C_DIM/4);
    split_kernel<<<(M_ROWS*C_DIM/4 + 255)/256, 256>>>(y, yh, yl, M_ROWS*C_DIM/4);
    split_kernel<<<(QKV_DIM*C_DIM/4 + 255)/256, 256>>>(w_qkv, wqh, wql, QKV_DIM*C_DIM/4);
    split_kernel<<<(C_DIM*C_DIM/4 + 255)/256, 256>>>(w_proj, wph, wpl, C_DIM*C_DIM/4);

    // 1) QKV projections (limb out), x/y batched in z
    dim3 g1(QKV_DIM / 128, M_ROWS / 128, 2);
    gemm_mma<<<g1, 256, GEMM_SMEM>>>(xh, xl, yh, yl, wqh, wql, nullptr,
                                     nullptr, nullptr,
                                     qxh, qxl, qyh, qyl,
                                     M_ROWS, QKV_DIM, C_DIM);

    // 2) fused dual-softmax attention (limb in/out)
    attention_mma<<<dim3(SEQ / 128, HEADS * 2, BATCH), 256, ATT_SMEM>>>();

    // 3) output projections + bias (fp32 out), branches batched in z
    dim3 g2(C_DIM / 128, M_ROWS / 128, 2);
    gemm_mma<<<g2, 256, GEMM_SMEM>>>(axh, axl, ayh, ayl, wph, wpl, b_proj,
                                     out, out + (size_t)M_ROWS * C_DIM,
                                     nullptr, nullptr, nullptr, nullptr,
                                     M_ROWS, C_DIM, C_DIM);
}

// round 7
// speedup vs baseline: 1.0188x; 1.0188x over previous
#include <cuda_runtime.h>
#include <cuda_bf16.h>
#include <cstdint>

#define C_DIM   768
#define QKV_DIM 3072
#define BATCH   4
#define SEQ     1024
#define HEADS   12
#define HD      64
#define M_ROWS  (BATCH*SEQ)   // 4096

typedef __nv_bfloat16 bf16;

// -------- scratch (allocation-free: device globals) --------
__device__ float g_qkv_x[M_ROWS*QKV_DIM];
__device__ float g_qkv_y[M_ROWS*QKV_DIM];
__device__ float g_att_x[M_ROWS*C_DIM];
__device__ float g_att_y[M_ROWS*C_DIM];
__device__ bf16 g_x_hi[M_ROWS*C_DIM],     g_x_lo[M_ROWS*C_DIM];
__device__ bf16 g_y_hi[M_ROWS*C_DIM],     g_y_lo[M_ROWS*C_DIM];
__device__ bf16 g_wqkv_hi[QKV_DIM*C_DIM], g_wqkv_lo[QKV_DIM*C_DIM];
__device__ bf16 g_wproj_hi[C_DIM*C_DIM],  g_wproj_lo[C_DIM*C_DIM];
__device__ bf16 g_ax_hi[M_ROWS*C_DIM],    g_ax_lo[M_ROWS*C_DIM];
__device__ bf16 g_ay_hi[M_ROWS*C_DIM],    g_ay_lo[M_ROWS*C_DIM];

// ============================================================
// helpers
// ============================================================
__device__ __forceinline__ uint32_t smem_u32(const void* p) {
    uint32_t a;
    asm("{ .reg .u64 t; cvta.to.shared.u64 t, %1; cvt.u32.u64 %0, t; }"
        : "=r"(a) : "l"(p));
    return a;
}

__device__ __forceinline__ void ldsm_x4(uint32_t addr, uint32_t& r0, uint32_t& r1,
                                        uint32_t& r2, uint32_t& r3) {
    asm volatile("ldmatrix.sync.aligned.m8n8.x4.shared.b16 {%0,%1,%2,%3}, [%4];"
                 : "=r"(r0), "=r"(r1), "=r"(r2), "=r"(r3) : "r"(addr));
}

__device__ __forceinline__ void mma_bf16(float* c, const uint32_t* a,
                                         uint32_t b0, uint32_t b1) {
    asm volatile(
        "mma.sync.aligned.m16n8k16.row.col.f32.bf16.bf16.f32 "
        "{%0,%1,%2,%3}, {%4,%5,%6,%7}, {%8,%9}, {%0,%1,%2,%3};"
        : "+f"(c[0]), "+f"(c[1]), "+f"(c[2]), "+f"(c[3])
        : "r"(a[0]), "r"(a[1]), "r"(a[2]), "r"(a[3]), "r"(b0), "r"(b1));
}

__device__ __forceinline__ void cp_async16(uint32_t saddr, const void* gptr) {
    asm volatile("cp.async.cg.shared.global [%0], [%1], 16;"
                 :: "r"(saddr), "l"(gptr));
}
__device__ __forceinline__ void cp_commit() {
    asm volatile("cp.async.commit_group;" ::: "memory");
}
__device__ __forceinline__ void cp_wait0() { asm volatile("cp.async.wait_group 0;" ::: "memory"); }
__device__ __forceinline__ void cp_wait1() { asm volatile("cp.async.wait_group 1;" ::: "memory"); }
__device__ __forceinline__ void cp_wait2() { asm volatile("cp.async.wait_group 2;" ::: "memory"); }

__device__ __forceinline__ uint32_t pack_bf2(bf16 a, bf16 b) {
    return ((uint32_t)__bfloat16_as_ushort(b) << 16) | (uint32_t)__bfloat16_as_ushort(a);
}

__device__ __forceinline__ void split4(float4 v, uint2& hi, uint2& lo) {
    bf16 h0 = __float2bfloat16_rn(v.x);
    bf16 h1 = __float2bfloat16_rn(v.y);
    bf16 h2 = __float2bfloat16_rn(v.z);
    bf16 h3 = __float2bfloat16_rn(v.w);
    bf16 l0 = __float2bfloat16_rn(v.x - __bfloat162float(h0));
    bf16 l1 = __float2bfloat16_rn(v.y - __bfloat162float(h1));
    bf16 l2 = __float2bfloat16_rn(v.z - __bfloat162float(h2));
    bf16 l3 = __float2bfloat16_rn(v.w - __bfloat162float(h3));
    hi.x = pack_bf2(h0, h1); hi.y = pack_bf2(h2, h3);
    lo.x = pack_bf2(l0, l1); lo.y = pack_bf2(l2, l3);
}

__device__ __forceinline__ void split2_pack(float a, float b, uint32_t& hi, uint32_t& lo) {
    bf16 h0 = __float2bfloat16_rn(a);
    bf16 h1 = __float2bfloat16_rn(b);
    hi = pack_bf2(h0, h1);
    lo = pack_bf2(__float2bfloat16_rn(a - __bfloat162float(h0)),
                  __float2bfloat16_rn(b - __bfloat162float(h1)));
}

// ============================================================
// fp32 -> limb split kernel (memory-bound pre-pass)
// ============================================================
__global__ __launch_bounds__(256) void split_kernel(
    const float* __restrict__ src, bf16* __restrict__ hi,
    bf16* __restrict__ lo, int n4)
{
    int i = blockIdx.x * 256 + threadIdx.x;
    if (i < n4) {
        float4 v = ((const float4*)src)[i];
        uint2 h, l;
        split4(v, h, l);
        ((uint2*)hi)[i] = h;
        ((uint2*)lo)[i] = l;
    }
}

// ============================================================
// split-bf16 mma.sync GEMM, limb inputs.
// CTA tile 128m x 256n, 8 warps (2m x 4n), warp tile 64x64.
// BK=16, 4-deep cp.async ring, 1 sync/stage.
// C[m,n] = sum_k A[m,k]*B[n,k] (+bias), fp32 out.
// ============================================================
#define LDH2 24                        // halves per row (16 + 8 pad)
#define ACH  (128 * LDH2)              // 3072 halves per A limb array
#define BCH  (256 * LDH2)              // 6144 halves per B limb array
#define STGH2 (2*ACH + 2*BCH)          // 18432 halves per stage
#define STGB  (STGH2 * 2)              // 36864 bytes per stage
#define GEMM_SMEM (4 * STGB)           // 147456

__global__ __launch_bounds__(256, 1) void gemm_mma(
    const bf16* __restrict__ Ah0, const bf16* __restrict__ Al0,
    const bf16* __restrict__ Ah1, const bf16* __restrict__ Al1,
    const bf16* __restrict__ Bh,  const bf16* __restrict__ Bl,
    const float* __restrict__ bias,
    float* __restrict__ C0, float* __restrict__ C1,
    int M, int N, int K)
{
    extern __shared__ __align__(16) bf16 sh[];
    const int tid  = threadIdx.x;
    const int wid  = tid >> 5;
    const int lane = tid & 31;
    const int m0 = blockIdx.y * 128, n0 = blockIdx.x * 256;
    const int wm = (wid & 1) * 64;       // warp m offset
    const int wn = (wid >> 1) * 64;      // warp n offset
    const int S  = K / 16;

    const bf16* A_h = blockIdx.z ? Ah1 : Ah0;
    const bf16* A_l = blockIdx.z ? Al1 : Al0;
    float*      C   = blockIdx.z ? C1  : C0;

    const uint32_t sbase = smem_u32(sh);

    // per-thread cp.async slots: row = tid>>1 (0..127), chunk c = (tid&1)*8 halves
    const int ld_row = tid >> 1;
    const int ld_c   = (tid & 1) << 3;

    auto issue_stage = [&](int s, int buf) {
        const int kb = s * 16;
        const uint32_t so = sbase + (uint32_t)buf * STGB;
        const uint32_t ro = (uint32_t)(ld_row * LDH2 + ld_c) * 2u;
        const uint32_t r2 = (uint32_t)((ld_row + 128) * LDH2 + ld_c) * 2u;
        const size_t ga  = (size_t)(m0 + ld_row) * K + kb + ld_c;
        const size_t gb  = (size_t)(n0 + ld_row) * K + kb + ld_c;
        const size_t gb2 = (size_t)(n0 + ld_row + 128) * K + kb + ld_c;
        cp_async16(so + ro,                        A_h + ga);
        cp_async16(so + (uint32_t)(ACH*2) + ro,    A_l + ga);
        cp_async16(so + (uint32_t)(2*ACH*2) + ro,  Bh + gb);
        cp_async16(so + (uint32_t)(2*ACH*2) + r2,  Bh + gb2);
        cp_async16(so + (uint32_t)((2*ACH+BCH)*2) + ro, Bl + gb);
        cp_async16(so + (uint32_t)((2*ACH+BCH)*2) + r2, Bl + gb2);
    };

    float acc[4][8][4];
#pragma unroll
    for (int i = 0; i < 4; i++)
#pragma unroll
        for (int j = 0; j < 8; j++)
#pragma unroll
            for (int r = 0; r < 4; r++) acc[i][j][r] = 0.f;

    // ldmatrix per-warp address components (halves)
    const int a_off = (wm + (lane & 15)) * LDH2 + ((lane >> 4) << 3);
    const int b_off = (wn + ((lane >> 4) << 3) + (lane & 7)) * LDH2 + (((lane >> 3) & 1) << 3);

    issue_stage(0, 0); cp_commit();
    issue_stage(1, 1); cp_commit();
    issue_stage(2, 2); cp_commit();

    for (int s = 0; s < S; s++) {
        if (s + 2 < S)      cp_wait2();
        else if (s + 1 < S) cp_wait1();
        else                cp_wait0();
        __syncthreads();
        if (s + 3 < S) { issue_stage(s + 3, (s + 3) & 3); cp_commit(); }

        const uint32_t stg = sbase + (uint32_t)((s & 3) * STGB);

        uint32_t ah[4][4], bh[8][2], t[4][4];   // t: al then bl (aliased)
#pragma unroll
        for (int mt = 0; mt < 4; mt++)
            ldsm_x4(stg + (uint32_t)(a_off + mt * 16 * LDH2) * 2u,
                    ah[mt][0], ah[mt][1], ah[mt][2], ah[mt][3]);
#pragma unroll
        for (int p = 0; p < 4; p++)
            ldsm_x4(stg + (uint32_t)(2*ACH + b_off + p * 16 * LDH2) * 2u,
                    bh[p*2][0], bh[p*2][1], bh[p*2+1][0], bh[p*2+1][1]);

        // pass 1: Ah * Bh
#pragma unroll
        for (int mt = 0; mt < 4; mt++)
#pragma unroll
            for (int nt = 0; nt < 8; nt++)
                mma_bf16(acc[mt][nt], ah[mt], bh[nt][0], bh[nt][1]);

        // pass 2: Al * Bh
#pragma unroll
        for (int mt = 0; mt < 4; mt++)
            ldsm_x4(stg + (uint32_t)(ACH + a_off + mt * 16 * LDH2) * 2u,
                    t[mt][0], t[mt][1], t[mt][2], t[mt][3]);
#pragma unroll
        for (int mt = 0; mt < 4; mt++)
#pragma unroll
            for (int nt = 0; nt < 8; nt++)
                mma_bf16(acc[mt][nt], t[mt], bh[nt][0], bh[nt][1]);

        // pass 3: Ah * Bl (bl overwrites bh's registers via t-reload pattern)
#pragma unroll
        for (int p = 0; p < 4; p++)
            ldsm_x4(stg + (uint32_t)(2*ACH + BCH + b_off + p * 16 * LDH2) * 2u,
                    bh[p*2][0], bh[p*2][1], bh[p*2+1][0], bh[p*2+1][1]);
#pragma unroll
        for (int mt = 0; mt < 4; mt++)
#pragma unroll
            for (int nt = 0; nt < 8; nt++)
                mma_bf16(acc[mt][nt], ah[mt], bh[nt][0], bh[nt][1]);
    }

    // ---- epilogue: fp32 (+bias) ----
#pragma unroll
    for (int mt = 0; mt < 4; mt++) {
        int row0 = m0 + wm + mt * 16 + (lane >> 2);
#pragma unroll
        for (int nt = 0; nt < 8; nt++) {
            int col = n0 + wn + nt * 8 + (lane & 3) * 2;
            float b0 = 0.f, b1 = 0.f;
            if (bias) { b0 = __ldg(bias + col); b1 = __ldg(bias + col + 1); }
            float2 v0 = make_float2(acc[mt][nt][0] + b0, acc[mt][nt][1] + b1);
            float2 v1 = make_float2(acc[mt][nt][2] + b0, acc[mt][nt][3] + b1);
            *(float2*)(C + (size_t)row0 * N + col)       = v0;
            *(float2*)(C + (size_t)(row0 + 8) * N + col) = v1;
        }
    }
}

// ============================================================
// Dual-softmax flash attention on mma.sync (R5 verbatim).
// Double-buffered K/V tiles, register prefetch, 1 sync/iter.
// ============================================================
#define AQS 72
#define OQ1H 0
#define OQ1L (128*AQS)
#define OQ2H (2*128*AQS)
#define OQ2L (3*128*AQS)
#define OKV  (4*128*AQS)
#define KVH  (4*64*AQS)
#define ATT_SMEM ((OKV + 2*KVH) * 2)     // 147456 bytes

__global__ __launch_bounds__(256, 1) void attention_mma()
{
    extern __shared__ __align__(16) bf16 sh[];
    const uint32_t sb = smem_u32(sh);
    const int tid  = threadIdx.x;
    const int wid  = tid >> 5;
    const int lane = tid & 31;
    const int wm   = wid * 16;

    const int b    = blockIdx.z;
    const int h    = blockIdx.y >> 1;
    const int pair = blockIdx.y & 1;
    const int q0   = blockIdx.x * 128;

    const float* bx = g_qkv_x + (size_t)b * SEQ * QKV_DIM;
    const float* by = g_qkv_y + (size_t)b * SEQ * QKV_DIM;
    const int hoff  = h * HD;

    const float *Q1src, *Q2src, *Ksrc;
    float* outp;
    if (pair == 0) { Q1src = bx + C_DIM; Q2src = by;  Ksrc = bx + 2 * C_DIM; outp = g_att_x; }
    else           { Q1src = by + C_DIM; Q2src = bx;  Ksrc = by + 2 * C_DIM; outp = g_att_y; }
    const float* Vsrc = bx + 3 * C_DIM;   // vy = vx in the reference

    const int v_jp = tid & 31;
    const int v_d0 = (tid >> 5) * 8;

#pragma unroll
    for (int u = 0; u < 8; u++) {
        int idx = u * 256 + tid;
        int row = idx >> 4;
        int c4  = (idx & 15) << 2;
        float4 v1 = *(const float4*)(Q1src + (size_t)(q0 + row) * QKV_DIM + hoff + c4);
        float4 v2 = *(const float4*)(Q2src + (size_t)(q0 + row) * QKV_DIM + hoff + c4);
        v1.x *= 0.125f; v1.y *= 0.125f; v1.z *= 0.125f; v1.w *= 0.125f;
        v2.x *= -0.125f; v2.y *= -0.125f; v2.z *= -0.125f; v2.w *= -0.125f;
        uint2 hi, lo;
        int off = row * AQS + c4;
        split4(v1, hi, lo);
        *(uint2*)(sh + OQ1H + off) = hi;
        *(uint2*)(sh + OQ1L + off) = lo;
        split4(v2, hi, lo);
        *(uint2*)(sh + OQ2H + off) = hi;
        *(uint2*)(sh + OQ2L + off) = lo;
    }

    {
#pragma unroll
        for (int u = 0; u < 4; u++) {
            int idx = u * 256 + tid;
            int row = idx >> 4;
            int c4  = (idx & 15) << 2;
            float4 kv = *(const float4*)(Ksrc + (size_t)row * QKV_DIM + hoff + c4);
            uint2 hi, lo;
            split4(kv, hi, lo);
            int off = row * AQS + c4;
            *(uint2*)(sh + OKV + off)            = hi;
            *(uint2*)(sh + OKV + 64*AQS + off)   = lo;
        }
        const float* v0p = Vsrc + (size_t)(2 * v_jp)     * QKV_DIM + hoff + v_d0;
        const float* v1p = Vsrc + (size_t)(2 * v_jp + 1) * QKV_DIM + hoff + v_d0;
        float4 va0 = *(const float4*)(v0p);
        float4 va1 = *(const float4*)(v0p + 4);
        float4 vb0 = *(const float4*)(v1p);
        float4 vb1 = *(const float4*)(v1p + 4);
        float f0[8] = {va0.x, va0.y, va0.z, va0.w, va1.x, va1.y, va1.z, va1.w};
        float f1[8] = {vb0.x, vb0.y, vb0.z, vb0.w, vb1.x, vb1.y, vb1.z, vb1.w};
#pragma unroll
        for (int i = 0; i < 8; i++) {
            bf16 h0 = __float2bfloat16_rn(f0[i]);
            bf16 h1 = __float2bfloat16_rn(f1[i]);
            bf16 e0 = __float2bfloat16_rn(f0[i] - __bfloat162float(h0));
            bf16 e1 = __float2bfloat16_rn(f1[i] - __bfloat162float(h1));
            *(uint32_t*)(sh + OKV + 2*64*AQS + (v_d0 + i) * AQS + 2 * v_jp) = pack_bf2(h0, h1);
            *(uint32_t*)(sh + OKV + 3*64*AQS + (v_d0 + i) * AQS + 2 * v_jp) = pack_bf2(e0, e1);
        }
    }
    __syncthreads();

    float o1[8][4], o2[8][4];
#pragma unroll
    for (int d = 0; d < 8; d++)
#pragma unroll
        for (int r = 0; r < 4; r++) { o1[d][r] = 0.f; o2[d][r] = 0.f; }
    float m1lo = -1e30f, m1hi = -1e30f, l1lo = 0.f, l1hi = 0.f;
    float m2lo = -1e30f, m2hi = -1e30f, l2lo = 0.f, l2hi = 0.f;

    const uint32_t a_base = (uint32_t)((wm + (lane & 15)) * AQS + ((lane >> 4) << 3)) * 2u;
    const uint32_t b_base = (uint32_t)((((lane >> 4) << 3) + (lane & 7)) * AQS
                                       + (((lane >> 3) & 1) << 3)) * 2u;

    for (int kt = 0; kt < 16; kt++) {
        const int cur = kt & 1;
        const uint32_t kvb = (uint32_t)(OKV + cur * KVH) * 2u;

        float4 kpre[4], vpre[4];
        if (kt < 15) {
            const int j0n = (kt + 1) * 64;
#pragma unroll
            for (int u = 0; u < 4; u++) {
                int idx = u * 256 + tid;
                int row = idx >> 4;
                int c4  = (idx & 15) << 2;
                kpre[u] = *(const float4*)(Ksrc + (size_t)(j0n + row) * QKV_DIM + hoff + c4);
            }
            const float* v0p = Vsrc + (size_t)(j0n + 2 * v_jp)     * QKV_DIM + hoff + v_d0;
            const float* v1p = Vsrc + (size_t)(j0n + 2 * v_jp + 1) * QKV_DIM + hoff + v_d0;
            vpre[0] = *(const float4*)(v0p);
            vpre[1] = *(const float4*)(v0p + 4);
            vpre[2] = *(const float4*)(v1p);
            vpre[3] = *(const float4*)(v1p + 4);
        }

        float s1[8][4], s2[8][4];
#pragma unroll
        for (int n = 0; n < 8; n++)
#pragma unroll
            for (int r = 0; r < 4; r++) { s1[n][r] = 0.f; s2[n][r] = 0.f; }

#pragma unroll
        for (int ks = 0; ks < 4; ks++) {
            const uint32_t kofs = (uint32_t)(ks * 16) * 2u;
            uint32_t a1h[4], a1l[4], a2h[4], a2l[4];
            ldsm_x4(sb + OQ1H*2u + a_base + kofs, a1h[0], a1h[1], a1h[2], a1h[3]);
            ldsm_x4(sb + OQ1L*2u + a_base + kofs, a1l[0], a1l[1], a1l[2], a1l[3]);
            ldsm_x4(sb + OQ2H*2u + a_base + kofs, a2h[0], a2h[1], a2h[2], a2h[3]);
            ldsm_x4(sb + OQ2L*2u + a_base + kofs, a2l[0], a2l[1], a2l[2], a2l[3]);
#pragma unroll
            for (int jt = 0; jt < 4; jt++) {
                uint32_t rb = sb + kvb + b_base + (uint32_t)(jt * 16 * AQS) * 2u + kofs;
                uint32_t bh[2][2], bl[2][2];
                ldsm_x4(rb,                         bh[0][0], bh[0][1], bh[1][0], bh[1][1]);
                ldsm_x4(rb + (uint32_t)(64*AQS)*2u, bl[0][0], bl[0][1], bl[1][0], bl[1][1]);
#pragma unroll
                for (int q = 0; q < 2; q++) {
                    int nt = jt * 2 + q;
                    mma_bf16(s1[nt], a1h, bh[q][0], bh[q][1]);
                    mma_bf16(s2[nt], a2h, bh[q][0], bh[q][1]);
                    mma_bf16(s1[nt], a1h, bl[q][0], bl[q][1]);
                    mma_bf16(s2[nt], a2h, bl[q][0], bl[q][1]);
                    mma_bf16(s1[nt], a1l, bh[q][0], bh[q][1]);
                    mma_bf16(s2[nt], a2l, bh[q][0], bh[q][1]);
                }
            }
        }

        if (kt < 15) {
            const int nb = OKV + (cur ^ 1) * KVH;
#pragma unroll
            for (int u = 0; u < 4; u++) {
                int idx = u * 256 + tid;
                int row = idx >> 4;
                int c4  = (idx & 15) << 2;
                uint2 hi, lo;
                split4(kpre[u], hi, lo);
                int off = row * AQS + c4;
                *(uint2*)(sh + nb + off)          = hi;
                *(uint2*)(sh + nb + 64*AQS + off) = lo;
            }
            float f0[8] = {vpre[0].x, vpre[0].y, vpre[0].z, vpre[0].w,
                           vpre[1].x, vpre[1].y, vpre[1].z, vpre[1].w};
            float f1[8] = {vpre[2].x, vpre[2].y, vpre[2].z, vpre[2].w,
                           vpre[3].x, vpre[3].y, vpre[3].z, vpre[3].w};
#pragma unroll
            for (int i = 0; i < 8; i++) {
                bf16 h0 = __float2bfloat16_rn(f0[i]);
                bf16 h1 = __float2bfloat16_rn(f1[i]);
                bf16 e0 = __float2bfloat16_rn(f0[i] - __bfloat162float(h0));
                bf16 e1 = __float2bfloat16_rn(f1[i] - __bfloat162float(h1));
                *(uint32_t*)(sh + nb + 2*64*AQS + (v_d0 + i) * AQS + 2 * v_jp) = pack_bf2(h0, h1);
                *(uint32_t*)(sh + nb + 3*64*AQS + (v_d0 + i) * AQS + 2 * v_jp) = pack_bf2(e0, e1);
            }
        }

        uint32_t p1h[8][2], p1l[8][2], p2h[8][2], p2l[8][2];
        {
            float mxlo = -1e30f, mxhi = -1e30f;
#pragma unroll
            for (int n = 0; n < 8; n++) {
                mxlo = fmaxf(mxlo, fmaxf(s1[n][0], s1[n][1]));
                mxhi = fmaxf(mxhi, fmaxf(s1[n][2], s1[n][3]));
            }
            mxlo = fmaxf(mxlo, __shfl_xor_sync(0xffffffffu, mxlo, 1));
            mxlo = fmaxf(mxlo, __shfl_xor_sync(0xffffffffu, mxlo, 2));
            mxhi = fmaxf(mxhi, __shfl_xor_sync(0xffffffffu, mxhi, 1));
            mxhi = fmaxf(mxhi, __shfl_xor_sync(0xffffffffu, mxhi, 2));
            float mnlo = fmaxf(m1lo, mxlo), mnhi = fmaxf(m1hi, mxhi);
            float clo = __expf(m1lo - mnlo), chi = __expf(m1hi - mnhi);
            m1lo = mnlo; m1hi = mnhi;
            float sl = 0.f, shh = 0.f;
#pragma unroll
            for (int n = 0; n < 8; n++) {
                float p0 = __expf(s1[n][0] - mnlo);
                float p1 = __expf(s1[n][1] - mnlo);
                float p2 = __expf(s1[n][2] - mnhi);
                float p3 = __expf(s1[n][3] - mnhi);
                sl += p0 + p1; shh += p2 + p3;
                uint32_t hh, ll;
                split2_pack(p0, p1, hh, ll);
                p1h[n][0] = hh; p1l[n][0] = ll;
                split2_pack(p2, p3, hh, ll);
                p1h[n][1] = hh; p1l[n][1] = ll;
            }
            sl  += __shfl_xor_sync(0xffffffffu, sl, 1);
            sl  += __shfl_xor_sync(0xffffffffu, sl, 2);
            shh += __shfl_xor_sync(0xffffffffu, shh, 1);
            shh += __shfl_xor_sync(0xffffffffu, shh, 2);
            l1lo = l1lo * clo + sl; l1hi = l1hi * chi + shh;
#pragma unroll
            for (int d = 0; d < 8; d++) {
                o1[d][0] *= clo; o1[d][1] *= clo;
                o1[d][2] *= chi; o1[d][3] *= chi;
            }
        }
        {
            float mxlo = -1e30f, mxhi = -1e30f;
#pragma unroll
            for (int n = 0; n < 8; n++) {
                mxlo = fmaxf(mxlo, fmaxf(s2[n][0], s2[n][1]));
                mxhi = fmaxf(mxhi, fmaxf(s2[n][2], s2[n][3]));
            }
            mxlo = fmaxf(mxlo, __shfl_xor_sync(0xffffffffu, mxlo, 1));
            mxlo = fmaxf(mxlo, __shfl_xor_sync(0xffffffffu, mxlo, 2));
            mxhi = fmaxf(mxhi, __shfl_xor_sync(0xffffffffu, mxhi, 1));
            mxhi = fmaxf(mxhi, __shfl_xor_sync(0xffffffffu, mxhi, 2));
            float mnlo = fmaxf(m2lo, mxlo), mnhi = fmaxf(m2hi, mxhi);
            float clo = __expf(m2lo - mnlo), chi = __expf(m2hi - mnhi);
            m2lo = mnlo; m2hi = mnhi;
            float sl = 0.f, shh = 0.f;
#pragma unroll
            for (int n = 0; n < 8; n++) {
                float p0 = __expf(s2[n][0] - mnlo);
                float p1 = __expf(s2[n][1] - mnlo);
                float p2 = __expf(s2[n][2] - mnhi);
                float p3 = __expf(s2[n][3] - mnhi);
                sl += p0 + p1; shh += p2 + p3;
                uint32_t hh, ll;
                split2_pack(p0, p1, hh, ll);
                p2h[n][0] = hh; p2l[n][0] = ll;
                split2_pack(p2, p3, hh, ll);
                p2h[n][1] = hh; p2l[n][1] = ll;
            }
            sl  += __shfl_xor_sync(0xffffffffu, sl, 1);
            sl  += __shfl_xor_sync(0xffffffffu, sl, 2);
            shh += __shfl_xor_sync(0xffffffffu, shh, 1);
            shh += __shfl_xor_sync(0xffffffffu, shh, 2);
            l2lo = l2lo * clo + sl; l2hi = l2hi * chi + shh;
#pragma unroll
            for (int d = 0; d < 8; d++) {
                o2[d][0] *= clo; o2[d][1] *= clo;
                o2[d][2] *= chi; o2[d][3] *= chi;
            }
        }

        const uint32_t vbase = kvb + (uint32_t)(2 * 64 * AQS) * 2u;
#pragma unroll
        for (int ks = 0; ks < 4; ks++) {
            uint32_t a1hf[4] = { p1h[2*ks][0], p1h[2*ks][1], p1h[2*ks+1][0], p1h[2*ks+1][1] };
            uint32_t a1lf[4] = { p1l[2*ks][0], p1l[2*ks][1], p1l[2*ks+1][0], p1l[2*ks+1][1] };
            uint32_t a2hf[4] = { p2h[2*ks][0], p2h[2*ks][1], p2h[2*ks+1][0], p2h[2*ks+1][1] };
            uint32_t a2lf[4] = { p2l[2*ks][0], p2l[2*ks][1], p2l[2*ks+1][0], p2l[2*ks+1][1] };
            const uint32_t kofs = (uint32_t)(ks * 16) * 2u;
#pragma unroll
            for (int dt2 = 0; dt2 < 4; dt2++) {
                uint32_t rb = sb + vbase + b_base + (uint32_t)(dt2 * 16 * AQS) * 2u + kofs;
                uint32_t vh[2][2], vl[2][2];
                ldsm_x4(rb,                         vh[0][0], vh[0][1], vh[1][0], vh[1][1]);
                ldsm_x4(rb + (uint32_t)(64*AQS)*2u, vl[0][0], vl[0][1], vl[1][0], vl[1][1]);
#pragma unroll
                for (int q = 0; q < 2; q++) {
                    int dt = dt2 * 2 + q;
                    mma_bf16(o1[dt], a1hf, vh[q][0], vh[q][1]);
                    mma_bf16(o2[dt], a2hf, vh[q][0], vh[q][1]);
                    mma_bf16(o1[dt], a1hf, vl[q][0], vl[q][1]);
                    mma_bf16(o2[dt], a2hf, vl[q][0], vl[q][1]);
                    mma_bf16(o1[dt], a1lf, vh[q][0], vh[q][1]);
                    mma_bf16(o2[dt], a2lf, vh[q][0], vh[q][1]);
                }
            }
        }

        if (kt < 15) __syncthreads();
    }

    const float i1lo = 1.f / l1lo, i1hi = 1.f / l1hi;
    const float i2lo = 1.f / l2lo, i2hi = 1.f / l2hi;
    float* obase = outp + (size_t)b * SEQ * C_DIM;
    const int r0 = q0 + wm + (lane >> 2);
    const int cb = hoff + (lane & 3) * 2;
#pragma unroll
    for (int dt = 0; dt < 8; dt++) {
        int col = cb + dt * 8;
        float2 vlo = make_float2(o1[dt][0] * i1lo + o2[dt][0] * i2lo,
                                 o1[dt][1] * i1lo + o2[dt][1] * i2lo);
        float2 vhi = make_float2(o1[dt][2] * i1hi + o2[dt][2] * i2hi,
                                 o1[dt][3] * i1hi + o2[dt][3] * i2hi);
        *(float2*)(obase + (size_t)r0 * C_DIM + col)       = vlo;
        *(float2*)(obase + (size_t)(r0 + 8) * C_DIM + col) = vhi;
    }
}

// ============================================================
extern "C" void kernel_launch(void* const* d_in, const int* in_sizes, int n_in,
                              void* d_out, int out_size)
{
    const float* x      = (const float*)d_in[0];
    const float* y      = (const float*)d_in[1];
    const float* w_qkv  = (const float*)d_in[2];
    const float* w_proj = (const float*)d_in[3];
    const float* b_proj = (const float*)d_in[4];
    float* out = (float*)d_out;

    float *qx, *qy, *ax, *ay;
    bf16 *xh, *xl, *yh, *yl, *wqh, *wql, *wph, *wpl;
    bf16 *axh, *axl, *ayh, *ayl;
    cudaGetSymbolAddress((void**)&qx,  g_qkv_x);
    cudaGetSymbolAddress((void**)&qy,  g_qkv_y);
    cudaGetSymbolAddress((void**)&ax,  g_att_x);
    cudaGetSymbolAddress((void**)&ay,  g_att_y);
    cudaGetSymbolAddress((void**)&xh,  g_x_hi);     cudaGetSymbolAddress((void**)&xl,  g_x_lo);
    cudaGetSymbolAddress((void**)&yh,  g_y_hi);     cudaGetSymbolAddress((void**)&yl,  g_y_lo);
    cudaGetSymbolAddress((void**)&wqh, g_wqkv_hi);  cudaGetSymbolAddress((void**)&wql, g_wqkv_lo);
    cudaGetSymbolAddress((void**)&wph, g_wproj_hi); cudaGetSymbolAddress((void**)&wpl, g_wproj_lo);
    cudaGetSymbolAddress((void**)&axh, g_ax_hi);    cudaGetSymbolAddress((void**)&axl, g_ax_lo);
    cudaGetSymbolAddress((void**)&ayh, g_ay_hi);    cudaGetSymbolAddress((void**)&ayl, g_ay_lo);

    cudaFuncSetAttribute(gemm_mma,
                         cudaFuncAttributeMaxDynamicSharedMemorySize, GEMM_SMEM);
    cudaFuncSetAttribute(attention_mma,
                         cudaFuncAttributeMaxDynamicSharedMemorySize, ATT_SMEM);

    // 0) fp32 -> limb pre-splits (inputs + weights)
    split_kernel<<<(M_ROWS*C_DIM/4 + 255)/256, 256>>>(x, xh, xl, M_ROWS*C_DIM/4);
    split_kernel<<<(M_ROWS*C_DIM/4 + 255)/256, 256>>>(y, yh, yl, M_ROWS*C_DIM/4);
    split_kernel<<<(QKV_DIM*C_DIM/4 + 255)/256, 256>>>(w_qkv, wqh, wql, QKV_DIM*C_DIM/4);
    split_kernel<<<(C_DIM*C_DIM/4 + 255)/256, 256>>>(w_proj, wph, wpl, C_DIM*C_DIM/4);

    // 1) QKV projections (limb in, fp32 out), x/y batched in z
    dim3 g1(QKV_DIM / 256, M_ROWS / 128, 2);
    gemm_mma<<<g1, 256, GEMM_SMEM>>>(xh, xl, yh, yl, wqh, wql, nullptr,
                                     qx, qy, M_ROWS, QKV_DIM, C_DIM);

    // 2) fused dual-softmax attention (fp32 in/out, R5)
    attention_mma<<<dim3(SEQ / 128, HEADS * 2, BATCH), 256, ATT_SMEM>>>();

    // 2b) split attention outputs to limbs for proj
    split_kernel<<<(M_ROWS*C_DIM/4 + 255)/256, 256>>>(ax, axh, axl, M_ROWS*C_DIM/4);
    split_kernel<<<(M_ROWS*C_DIM/4 + 255)/256, 256>>>(ay, ayh, ayl, M_ROWS*C_DIM/4);

    // 3) output projections + bias (limb in, fp32 out), batched in z
    dim3 g2(C_DIM / 256, M_ROWS / 128, 2);
    gemm_mma<<<g2, 256, GEMM_SMEM>>>(axh, axl, ayh, ayl, wph, wpl, b_proj,
                                     out, out + (size_t)M_ROWS * C_DIM,
                                     M_ROWS, C_DIM, C_DIM);
}

// round 8
// speedup vs baseline: 1.4073x; 1.3814x over previous
#include <cuda_runtime.h>
#include <cuda_fp16.h>
#include <cstdint>

#define C_DIM   768
#define QKV_DIM 3072
#define BATCH   4
#define SEQ     1024
#define HEADS   12
#define HD      64
#define M_ROWS  (BATCH*SEQ)   // 4096

// -------- scratch (allocation-free: device globals) --------
__device__ float g_qkv_x[M_ROWS*QKV_DIM];
__device__ float g_qkv_y[M_ROWS*QKV_DIM];
__device__ float g_att_x[M_ROWS*C_DIM];
__device__ float g_att_y[M_ROWS*C_DIM];
__device__ __half g_x_hi[M_ROWS*C_DIM],     g_x_lo[M_ROWS*C_DIM];
__device__ __half g_y_hi[M_ROWS*C_DIM],     g_y_lo[M_ROWS*C_DIM];
__device__ __half g_wqkv_hi[QKV_DIM*C_DIM], g_wqkv_lo[QKV_DIM*C_DIM];
__device__ __half g_wproj_hi[C_DIM*C_DIM],  g_wproj_lo[C_DIM*C_DIM];
__device__ __half g_ax_hi[M_ROWS*C_DIM],    g_ax_lo[M_ROWS*C_DIM];
__device__ __half g_ay_hi[M_ROWS*C_DIM],    g_ay_lo[M_ROWS*C_DIM];

// ============================================================
// helpers
// ============================================================
__device__ __forceinline__ uint32_t smem_u32(const void* p) {
    uint32_t a;
    asm("{ .reg .u64 t; cvta.to.shared.u64 t, %1; cvt.u32.u64 %0, t; }"
        : "=r"(a) : "l"(p));
    return a;
}

__device__ __forceinline__ void ldsm_x4(uint32_t addr, uint32_t& r0, uint32_t& r1,
                                        uint32_t& r2, uint32_t& r3) {
    asm volatile("ldmatrix.sync.aligned.m8n8.x4.shared.b16 {%0,%1,%2,%3}, [%4];"
                 : "=r"(r0), "=r"(r1), "=r"(r2), "=r"(r3) : "r"(addr));
}

__device__ __forceinline__ void mma_f16(float* c, const uint32_t* a,
                                        uint32_t b0, uint32_t b1) {
    asm volatile(
        "mma.sync.aligned.m16n8k16.row.col.f32.f16.f16.f32 "
        "{%0,%1,%2,%3}, {%4,%5,%6,%7}, {%8,%9}, {%0,%1,%2,%3};"
        : "+f"(c[0]), "+f"(c[1]), "+f"(c[2]), "+f"(c[3])
        : "r"(a[0]), "r"(a[1]), "r"(a[2]), "r"(a[3]), "r"(b0), "r"(b1));
}

__device__ __forceinline__ void cp_async16(uint32_t saddr, const void* gptr) {
    asm volatile("cp.async.cg.shared.global [%0], [%1], 16;"
                 :: "r"(saddr), "l"(gptr));
}
__device__ __forceinline__ void cp_commit() {
    asm volatile("cp.async.commit_group;" ::: "memory");
}
__device__ __forceinline__ void cp_wait0() { asm volatile("cp.async.wait_group 0;" ::: "memory"); }
__device__ __forceinline__ void cp_wait1() { asm volatile("cp.async.wait_group 1;" ::: "memory"); }
__device__ __forceinline__ void cp_wait2() { asm volatile("cp.async.wait_group 2;" ::: "memory"); }

__device__ __forceinline__ uint32_t pack_h2(__half a, __half b) {
    return ((uint32_t)__half_as_ushort(b) << 16) | (uint32_t)__half_as_ushort(a);
}

// split fp32 float4 -> hi/lo fp16 limb pairs
__device__ __forceinline__ void split4h(float4 v, uint2& hi, uint2& lo) {
    __half h0 = __float2half_rn(v.x);
    __half h1 = __float2half_rn(v.y);
    __half h2 = __float2half_rn(v.z);
    __half h3 = __float2half_rn(v.w);
    __half l0 = __float2half_rn(v.x - __half2float(h0));
    __half l1 = __float2half_rn(v.y - __half2float(h1));
    __half l2 = __float2half_rn(v.z - __half2float(h2));
    __half l3 = __float2half_rn(v.w - __half2float(h3));
    hi.x = pack_h2(h0, h1); hi.y = pack_h2(h2, h3);
    lo.x = pack_h2(l0, l1); lo.y = pack_h2(l2, l3);
}

// fp32 float4 -> fp16 hi only (for K tiles: lo term dropped in 2-pass)
__device__ __forceinline__ uint2 hi4h(float4 v) {
    return make_uint2(pack_h2(__float2half_rn(v.x), __float2half_rn(v.y)),
                      pack_h2(__float2half_rn(v.z), __float2half_rn(v.w)));
}

// ============================================================
// fp32 -> fp16 limb split kernel (memory-bound pre-pass)
// ============================================================
__global__ __launch_bounds__(256) void split_kernel(
    const float* __restrict__ src, __half* __restrict__ hi,
    __half* __restrict__ lo, int n4)
{
    int i = blockIdx.x * 256 + threadIdx.x;
    if (i < n4) {
        float4 v = ((const float4*)src)[i];
        uint2 h, l;
        split4h(v, h, l);
        ((uint2*)hi)[i] = h;
        ((uint2*)lo)[i] = l;
    }
}

// ============================================================
// split-fp16 mma.sync GEMM, limb inputs.
// CTA tile 128m x 256n, 8 warps (2m x 4n), warp tile 64x64.
// BK=16, 4-deep cp.async ring, 1 sync/stage.
// NPASS=2: AhBh + AlBh (B-lo dropped). NPASS=3: + AhBl.
// ============================================================
#define LDH2 24                        // halves per row (16 + 8 pad)
#define ACH  (128 * LDH2)              // 3072 halves per A limb array
#define BCH  (256 * LDH2)              // 6144 halves per B limb array
#define STGH2 (2*ACH + 2*BCH)          // 18432 halves per stage
#define STGB  (STGH2 * 2)              // 36864 bytes per stage
#define GEMM_SMEM (4 * STGB)           // 147456

template<int NPASS>
__global__ __launch_bounds__(256, 1) void gemm_mma(
    const __half* __restrict__ Ah0, const __half* __restrict__ Al0,
    const __half* __restrict__ Ah1, const __half* __restrict__ Al1,
    const __half* __restrict__ Bh,  const __half* __restrict__ Bl,
    const float* __restrict__ bias,
    float* __restrict__ C0, float* __restrict__ C1,
    int M, int N, int K, int n_lim1)
{
    extern __shared__ __align__(16) __half sh[];
    const int tid  = threadIdx.x;
    const int wid  = tid >> 5;
    const int lane = tid & 31;
    const int m0 = blockIdx.y * 128, n0 = blockIdx.x * 256;
    if (blockIdx.z && n0 >= n_lim1) return;   // vy skip for y-QKV
    const int wm = (wid & 1) * 64;
    const int wn = (wid >> 1) * 64;
    const int S  = K / 16;

    const __half* A_h = blockIdx.z ? Ah1 : Ah0;
    const __half* A_l = blockIdx.z ? Al1 : Al0;
    float*        C   = blockIdx.z ? C1  : C0;

    const uint32_t sbase = smem_u32(sh);
    const int ld_row = tid >> 1;
    const int ld_c   = (tid & 1) << 3;

    auto issue_stage = [&](int s, int buf) {
        const int kb = s * 16;
        const uint32_t so = sbase + (uint32_t)buf * STGB;
        const uint32_t ro = (uint32_t)(ld_row * LDH2 + ld_c) * 2u;
        const uint32_t r2 = (uint32_t)((ld_row + 128) * LDH2 + ld_c) * 2u;
        const size_t ga  = (size_t)(m0 + ld_row) * K + kb + ld_c;
        const size_t gb  = (size_t)(n0 + ld_row) * K + kb + ld_c;
        const size_t gb2 = (size_t)(n0 + ld_row + 128) * K + kb + ld_c;
        cp_async16(so + ro,                        A_h + ga);
        cp_async16(so + (uint32_t)(ACH*2) + ro,    A_l + ga);
        cp_async16(so + (uint32_t)(2*ACH*2) + ro,  Bh + gb);
        cp_async16(so + (uint32_t)(2*ACH*2) + r2,  Bh + gb2);
        if (NPASS == 3) {
            cp_async16(so + (uint32_t)((2*ACH+BCH)*2) + ro, Bl + gb);
            cp_async16(so + (uint32_t)((2*ACH+BCH)*2) + r2, Bl + gb2);
        }
    };

    float acc[4][8][4];
#pragma unroll
    for (int i = 0; i < 4; i++)
#pragma unroll
        for (int j = 0; j < 8; j++)
#pragma unroll
            for (int r = 0; r < 4; r++) acc[i][j][r] = 0.f;

    const int a_off = (wm + (lane & 15)) * LDH2 + ((lane >> 4) << 3);
    const int b_off = (wn + ((lane >> 4) << 3) + (lane & 7)) * LDH2 + (((lane >> 3) & 1) << 3);

    issue_stage(0, 0); cp_commit();
    issue_stage(1, 1); cp_commit();
    issue_stage(2, 2); cp_commit();

    for (int s = 0; s < S; s++) {
        if (s + 2 < S)      cp_wait2();
        else if (s + 1 < S) cp_wait1();
        else                cp_wait0();
        __syncthreads();
        if (s + 3 < S) { issue_stage(s + 3, (s + 3) & 3); cp_commit(); }

        const uint32_t stg = sbase + (uint32_t)((s & 3) * STGB);

        uint32_t ah[4][4], bh[8][2], t[4][4];
#pragma unroll
        for (int mt = 0; mt < 4; mt++)
            ldsm_x4(stg + (uint32_t)(a_off + mt * 16 * LDH2) * 2u,
                    ah[mt][0], ah[mt][1], ah[mt][2], ah[mt][3]);
#pragma unroll
        for (int p = 0; p < 4; p++)
            ldsm_x4(stg + (uint32_t)(2*ACH + b_off + p * 16 * LDH2) * 2u,
                    bh[p*2][0], bh[p*2][1], bh[p*2+1][0], bh[p*2+1][1]);

        // pass 1: Ah * Bh
#pragma unroll
        for (int mt = 0; mt < 4; mt++)
#pragma unroll
            for (int nt = 0; nt < 8; nt++)
                mma_f16(acc[mt][nt], ah[mt], bh[nt][0], bh[nt][1]);

        // pass 2: Al * Bh
#pragma unroll
        for (int mt = 0; mt < 4; mt++)
            ldsm_x4(stg + (uint32_t)(ACH + a_off + mt * 16 * LDH2) * 2u,
                    t[mt][0], t[mt][1], t[mt][2], t[mt][3]);
#pragma unroll
        for (int mt = 0; mt < 4; mt++)
#pragma unroll
            for (int nt = 0; nt < 8; nt++)
                mma_f16(acc[mt][nt], t[mt], bh[nt][0], bh[nt][1]);

        if (NPASS == 3) {
            // pass 3: Ah * Bl
#pragma unroll
            for (int p = 0; p < 4; p++)
                ldsm_x4(stg + (uint32_t)(2*ACH + BCH + b_off + p * 16 * LDH2) * 2u,
                        bh[p*2][0], bh[p*2][1], bh[p*2+1][0], bh[p*2+1][1]);
#pragma unroll
            for (int mt = 0; mt < 4; mt++)
#pragma unroll
                for (int nt = 0; nt < 8; nt++)
                    mma_f16(acc[mt][nt], ah[mt], bh[nt][0], bh[nt][1]);
        }
    }

    // ---- epilogue: fp32 (+bias) ----
#pragma unroll
    for (int mt = 0; mt < 4; mt++) {
        int row0 = m0 + wm + mt * 16 + (lane >> 2);
#pragma unroll
        for (int nt = 0; nt < 8; nt++) {
            int col = n0 + wn + nt * 8 + (lane & 3) * 2;
            float b0 = 0.f, b1 = 0.f;
            if (bias) { b0 = __ldg(bias + col); b1 = __ldg(bias + col + 1); }
            float2 v0 = make_float2(acc[mt][nt][0] + b0, acc[mt][nt][1] + b1);
            float2 v1 = make_float2(acc[mt][nt][2] + b0, acc[mt][nt][3] + b1);
            *(float2*)(C + (size_t)row0 * N + col)       = v0;
            *(float2*)(C + (size_t)(row0 + 8) * N + col) = v1;
        }
    }
}

// ============================================================
// Dual-softmax flash attention, fp16 2-pass limbs.
// Q: hi+lo; K: hi only; V: hi+lo; P: hi only.
// Double-buffered K/V, register prefetch, 1 sync/iter.
// ============================================================
#define AQS 72
#define OQ1H 0
#define OQ1L (128*AQS)
#define OQ2H (2*128*AQS)
#define OQ2L (3*128*AQS)
#define OKV  (4*128*AQS)
#define KVH  (3*64*AQS)                   // Kh, Vh, Vl
#define ATT_SMEM ((OKV + 2*KVH) * 2)      // 129024 bytes

__global__ __launch_bounds__(256, 1) void attention_mma()
{
    extern __shared__ __align__(16) __half sh[];
    const uint32_t sb = smem_u32(sh);
    const int tid  = threadIdx.x;
    const int wid  = tid >> 5;
    const int lane = tid & 31;
    const int wm   = wid * 16;

    const int b    = blockIdx.z;
    const int h    = blockIdx.y >> 1;
    const int pair = blockIdx.y & 1;
    const int q0   = blockIdx.x * 128;

    const float* bx = g_qkv_x + (size_t)b * SEQ * QKV_DIM;
    const float* by = g_qkv_y + (size_t)b * SEQ * QKV_DIM;
    const int hoff  = h * HD;

    const float *Q1src, *Q2src, *Ksrc;
    float* outp;
    if (pair == 0) { Q1src = bx + C_DIM; Q2src = by;  Ksrc = bx + 2 * C_DIM; outp = g_att_x; }
    else           { Q1src = by + C_DIM; Q2src = bx;  Ksrc = by + 2 * C_DIM; outp = g_att_y; }
    const float* Vsrc = bx + 3 * C_DIM;   // vy = vx in the reference

    const int v_jp = tid & 31;
    const int v_d0 = (tid >> 5) * 8;

    // ---- load Q tiles as pre-scaled fp16 limbs ----
#pragma unroll
    for (int u = 0; u < 8; u++) {
        int idx = u * 256 + tid;
        int row = idx >> 4;
        int c4  = (idx & 15) << 2;
        float4 v1 = *(const float4*)(Q1src + (size_t)(q0 + row) * QKV_DIM + hoff + c4);
        float4 v2 = *(const float4*)(Q2src + (size_t)(q0 + row) * QKV_DIM + hoff + c4);
        v1.x *= 0.125f; v1.y *= 0.125f; v1.z *= 0.125f; v1.w *= 0.125f;
        v2.x *= -0.125f; v2.y *= -0.125f; v2.z *= -0.125f; v2.w *= -0.125f;
        uint2 hi, lo;
        int off = row * AQS + c4;
        split4h(v1, hi, lo);
        *(uint2*)(sh + OQ1H + off) = hi;
        *(uint2*)(sh + OQ1L + off) = lo;
        split4h(v2, hi, lo);
        *(uint2*)(sh + OQ2H + off) = hi;
        *(uint2*)(sh + OQ2L + off) = lo;
    }

    // ---- load KV tile 0 ----
    {
#pragma unroll
        for (int u = 0; u < 4; u++) {
            int idx = u * 256 + tid;
            int row = idx >> 4;
            int c4  = (idx & 15) << 2;
            float4 kv = *(const float4*)(Ksrc + (size_t)row * QKV_DIM + hoff + c4);
            *(uint2*)(sh + OKV + row * AQS + c4) = hi4h(kv);
        }
        const float* v0p = Vsrc + (size_t)(2 * v_jp)     * QKV_DIM + hoff + v_d0;
        const float* v1p = Vsrc + (size_t)(2 * v_jp + 1) * QKV_DIM + hoff + v_d0;
        float4 va0 = *(const float4*)(v0p);
        float4 va1 = *(const float4*)(v0p + 4);
        float4 vb0 = *(const float4*)(v1p);
        float4 vb1 = *(const float4*)(v1p + 4);
        float f0[8] = {va0.x, va0.y, va0.z, va0.w, va1.x, va1.y, va1.z, va1.w};
        float f1[8] = {vb0.x, vb0.y, vb0.z, vb0.w, vb1.x, vb1.y, vb1.z, vb1.w};
#pragma unroll
        for (int i = 0; i < 8; i++) {
            __half h0 = __float2half_rn(f0[i]);
            __half h1 = __float2half_rn(f1[i]);
            __half e0 = __float2half_rn(f0[i] - __half2float(h0));
            __half e1 = __float2half_rn(f1[i] - __half2float(h1));
            *(uint32_t*)(sh + OKV + 64*AQS   + (v_d0 + i) * AQS + 2 * v_jp) = pack_h2(h0, h1);
            *(uint32_t*)(sh + OKV + 2*64*AQS + (v_d0 + i) * AQS + 2 * v_jp) = pack_h2(e0, e1);
        }
    }
    __syncthreads();

    float o1[8][4], o2[8][4];
#pragma unroll
    for (int d = 0; d < 8; d++)
#pragma unroll
        for (int r = 0; r < 4; r++) { o1[d][r] = 0.f; o2[d][r] = 0.f; }
    float m1lo = -1e30f, m1hi = -1e30f, l1lo = 0.f, l1hi = 0.f;
    float m2lo = -1e30f, m2hi = -1e30f, l2lo = 0.f, l2hi = 0.f;

    const uint32_t a_base = (uint32_t)((wm + (lane & 15)) * AQS + ((lane >> 4) << 3)) * 2u;
    const uint32_t b_base = (uint32_t)((((lane >> 4) << 3) + (lane & 7)) * AQS
                                       + (((lane >> 3) & 1) << 3)) * 2u;

    for (int kt = 0; kt < 16; kt++) {
        const int cur = kt & 1;
        const uint32_t kvb = (uint32_t)(OKV + cur * KVH) * 2u;

        // ---- prefetch next KV tile into registers ----
        float4 kpre[4], vpre[4];
        if (kt < 15) {
            const int j0n = (kt + 1) * 64;
#pragma unroll
            for (int u = 0; u < 4; u++) {
                int idx = u * 256 + tid;
                int row = idx >> 4;
                int c4  = (idx & 15) << 2;
                kpre[u] = *(const float4*)(Ksrc + (size_t)(j0n + row) * QKV_DIM + hoff + c4);
            }
            const float* v0p = Vsrc + (size_t)(j0n + 2 * v_jp)     * QKV_DIM + hoff + v_d0;
            const float* v1p = Vsrc + (size_t)(j0n + 2 * v_jp + 1) * QKV_DIM + hoff + v_d0;
            vpre[0] = *(const float4*)(v0p);
            vpre[1] = *(const float4*)(v0p + 4);
            vpre[2] = *(const float4*)(v1p);
            vpre[3] = *(const float4*)(v1p + 4);
        }

        // ---- S = Q K^T (2-pass: Qh*Kh + Ql*Kh), stream-interleaved ----
        float s1[8][4], s2[8][4];
#pragma unroll
        for (int n = 0; n < 8; n++)
#pragma unroll
            for (int r = 0; r < 4; r++) { s1[n][r] = 0.f; s2[n][r] = 0.f; }

#pragma unroll
        for (int ks = 0; ks < 4; ks++) {
            const uint32_t kofs = (uint32_t)(ks * 16) * 2u;
            uint32_t a1h[4], a1l[4], a2h[4], a2l[4];
            ldsm_x4(sb + OQ1H*2u + a_base + kofs, a1h[0], a1h[1], a1h[2], a1h[3]);
            ldsm_x4(sb + OQ1L*2u + a_base + kofs, a1l[0], a1l[1], a1l[2], a1l[3]);
            ldsm_x4(sb + OQ2H*2u + a_base + kofs, a2h[0], a2h[1], a2h[2], a2h[3]);
            ldsm_x4(sb + OQ2L*2u + a_base + kofs, a2l[0], a2l[1], a2l[2], a2l[3]);
#pragma unroll
            for (int jt = 0; jt < 4; jt++) {
                uint32_t rb = sb + kvb + b_base + (uint32_t)(jt * 16 * AQS) * 2u + kofs;
                uint32_t bh[2][2];
                ldsm_x4(rb, bh[0][0], bh[0][1], bh[1][0], bh[1][1]);
#pragma unroll
                for (int q = 0; q < 2; q++) {
                    int nt = jt * 2 + q;
                    mma_f16(s1[nt], a1h, bh[q][0], bh[q][1]);
                    mma_f16(s2[nt], a2h, bh[q][0], bh[q][1]);
                    mma_f16(s1[nt], a1l, bh[q][0], bh[q][1]);
                    mma_f16(s2[nt], a2l, bh[q][0], bh[q][1]);
                }
            }
        }

        // ---- store prefetched tile into the other buffer ----
        if (kt < 15) {
            const int nb = OKV + (cur ^ 1) * KVH;
#pragma unroll
            for (int u = 0; u < 4; u++) {
                int idx = u * 256 + tid;
                int row = idx >> 4;
                int c4  = (idx & 15) << 2;
                *(uint2*)(sh + nb + row * AQS + c4) = hi4h(kpre[u]);
            }
            float f0[8] = {vpre[0].x, vpre[0].y, vpre[0].z, vpre[0].w,
                           vpre[1].x, vpre[1].y, vpre[1].z, vpre[1].w};
            float f1[8] = {vpre[2].x, vpre[2].y, vpre[2].z, vpre[2].w,
                           vpre[3].x, vpre[3].y, vpre[3].z, vpre[3].w};
#pragma unroll
            for (int i = 0; i < 8; i++) {
                __half h0 = __float2half_rn(f0[i]);
                __half h1 = __float2half_rn(f1[i]);
                __half e0 = __float2half_rn(f0[i] - __half2float(h0));
                __half e1 = __float2half_rn(f1[i] - __half2float(h1));
                *(uint32_t*)(sh + nb + 64*AQS   + (v_d0 + i) * AQS + 2 * v_jp) = pack_h2(h0, h1);
                *(uint32_t*)(sh + nb + 2*64*AQS + (v_d0 + i) * AQS + 2 * v_jp) = pack_h2(e0, e1);
            }
        }

        // ---- online softmax (per stream), P as fp16 hi only ----
        uint32_t p1h[8][2], p2h[8][2];
        {
            float mxlo = -1e30f, mxhi = -1e30f;
#pragma unroll
            for (int n = 0; n < 8; n++) {
                mxlo = fmaxf(mxlo, fmaxf(s1[n][0], s1[n][1]));
                mxhi = fmaxf(mxhi, fmaxf(s1[n][2], s1[n][3]));
            }
            mxlo = fmaxf(mxlo, __shfl_xor_sync(0xffffffffu, mxlo, 1));
            mxlo = fmaxf(mxlo, __shfl_xor_sync(0xffffffffu, mxlo, 2));
            mxhi = fmaxf(mxhi, __shfl_xor_sync(0xffffffffu, mxhi, 1));
            mxhi = fmaxf(mxhi, __shfl_xor_sync(0xffffffffu, mxhi, 2));
            float mnlo = fmaxf(m1lo, mxlo), mnhi = fmaxf(m1hi, mxhi);
            float clo = __expf(m1lo - mnlo), chi = __expf(m1hi - mnhi);
            m1lo = mnlo; m1hi = mnhi;
            float sl = 0.f, shh = 0.f;
#pragma unroll
            for (int n = 0; n < 8; n++) {
                float p0 = __expf(s1[n][0] - mnlo);
                float p1 = __expf(s1[n][1] - mnlo);
                float p2 = __expf(s1[n][2] - mnhi);
                float p3 = __expf(s1[n][3] - mnhi);
                sl += p0 + p1; shh += p2 + p3;
                p1h[n][0] = pack_h2(__float2half_rn(p0), __float2half_rn(p1));
                p1h[n][1] = pack_h2(__float2half_rn(p2), __float2half_rn(p3));
            }
            sl  += __shfl_xor_sync(0xffffffffu, sl, 1);
            sl  += __shfl_xor_sync(0xffffffffu, sl, 2);
            shh += __shfl_xor_sync(0xffffffffu, shh, 1);
            shh += __shfl_xor_sync(0xffffffffu, shh, 2);
            l1lo = l1lo * clo + sl; l1hi = l1hi * chi + shh;
#pragma unroll
            for (int d = 0; d < 8; d++) {
                o1[d][0] *= clo; o1[d][1] *= clo;
                o1[d][2] *= chi; o1[d][3] *= chi;
            }
        }
        {
            float mxlo = -1e30f, mxhi = -1e30f;
#pragma unroll
            for (int n = 0; n < 8; n++) {
                mxlo = fmaxf(mxlo, fmaxf(s2[n][0], s2[n][1]));
                mxhi = fmaxf(mxhi, fmaxf(s2[n][2], s2[n][3]));
            }
            mxlo = fmaxf(mxlo, __shfl_xor_sync(0xffffffffu, mxlo, 1));
            mxlo = fmaxf(mxlo, __shfl_xor_sync(0xffffffffu, mxlo, 2));
            mxhi = fmaxf(mxhi, __shfl_xor_sync(0xffffffffu, mxhi, 1));
            mxhi = fmaxf(mxhi, __shfl_xor_sync(0xffffffffu, mxhi, 2));
            float mnlo = fmaxf(m2lo, mxlo), mnhi = fmaxf(m2hi, mxhi);
            float clo = __expf(m2lo - mnlo), chi = __expf(m2hi - mnhi);
            m2lo = mnlo; m2hi = mnhi;
            float sl = 0.f, shh = 0.f;
#pragma unroll
            for (int n = 0; n < 8; n++) {
                float p0 = __expf(s2[n][0] - mnlo);
                float p1 = __expf(s2[n][1] - mnlo);
                float p2 = __expf(s2[n][2] - mnhi);
                float p3 = __expf(s2[n][3] - mnhi);
                sl += p0 + p1; shh += p2 + p3;
                p2h[n][0] = pack_h2(__float2half_rn(p0), __float2half_rn(p1));
                p2h[n][1] = pack_h2(__float2half_rn(p2), __float2half_rn(p3));
            }
            sl  += __shfl_xor_sync(0xffffffffu, sl, 1);
            sl  += __shfl_xor_sync(0xffffffffu, sl, 2);
            shh += __shfl_xor_sync(0xffffffffu, shh, 1);
            shh += __shfl_xor_sync(0xffffffffu, shh, 2);
            l2lo = l2lo * clo + sl; l2hi = l2hi * chi + shh;
#pragma unroll
            for (int d = 0; d < 8; d++) {
                o2[d][0] *= clo; o2[d][1] *= clo;
                o2[d][2] *= chi; o2[d][3] *= chi;
            }
        }

        // ---- O += P V (2-pass: Ph*Vh + Ph*Vl) ----
#pragma unroll
        for (int ks = 0; ks < 4; ks++) {
            uint32_t a1f[4] = { p1h[2*ks][0], p1h[2*ks][1], p1h[2*ks+1][0], p1h[2*ks+1][1] };
            uint32_t a2f[4] = { p2h[2*ks][0], p2h[2*ks][1], p2h[2*ks+1][0], p2h[2*ks+1][1] };
            const uint32_t kofs = (uint32_t)(ks * 16) * 2u;
#pragma unroll
            for (int dt2 = 0; dt2 < 4; dt2++) {
                uint32_t rb = sb + kvb + (uint32_t)(64*AQS)*2u + b_base
                            + (uint32_t)(dt2 * 16 * AQS) * 2u + kofs;
                uint32_t vh[2][2], vl[2][2];
                ldsm_x4(rb,                         vh[0][0], vh[0][1], vh[1][0], vh[1][1]);
                ldsm_x4(rb + (uint32_t)(64*AQS)*2u, vl[0][0], vl[0][1], vl[1][0], vl[1][1]);
#pragma unroll
                for (int q = 0; q < 2; q++) {
                    int dt = dt2 * 2 + q;
                    mma_f16(o1[dt], a1f, vh[q][0], vh[q][1]);
                    mma_f16(o2[dt], a2f, vh[q][0], vh[q][1]);
                    mma_f16(o1[dt], a1f, vl[q][0], vl[q][1]);
                    mma_f16(o2[dt], a2f, vl[q][0], vl[q][1]);
                }
            }
        }

        if (kt < 15) __syncthreads();
    }

    // ---- epilogue: out = O1/l1 + O2/l2 (fp32) ----
    const float i1lo = 1.f / l1lo, i1hi = 1.f / l1hi;
    const float i2lo = 1.f / l2lo, i2hi = 1.f / l2hi;
    float* obase = outp + (size_t)b * SEQ * C_DIM;
    const int r0 = q0 + wm + (lane >> 2);
    const int hoff2 = h * HD;
    const int cb = hoff2 + (lane & 3) * 2;
#pragma unroll
    for (int dt = 0; dt < 8; dt++) {
        int col = cb + dt * 8;
        float2 vlo = make_float2(o1[dt][0] * i1lo + o2[dt][0] * i2lo,
                                 o1[dt][1] * i1lo + o2[dt][1] * i2lo);
        float2 vhi = make_float2(o1[dt][2] * i1hi + o2[dt][2] * i2hi,
                                 o1[dt][3] * i1hi + o2[dt][3] * i2hi);
        *(float2*)(obase + (size_t)r0 * C_DIM + col)       = vlo;
        *(float2*)(obase + (size_t)(r0 + 8) * C_DIM + col) = vhi;
    }
}

// ============================================================
extern "C" void kernel_launch(void* const* d_in, const int* in_sizes, int n_in,
                              void* d_out, int out_size)
{
    const float* x      = (const float*)d_in[0];
    const float* y      = (const float*)d_in[1];
    const float* w_qkv  = (const float*)d_in[2];
    const float* w_proj = (const float*)d_in[3];
    const float* b_proj = (const float*)d_in[4];
    float* out = (float*)d_out;

    float *qx, *qy, *ax, *ay;
    __half *xh, *xl, *yh, *yl, *wqh, *wql, *wph, *wpl;
    __half *axh, *axl, *ayh, *ayl;
    cudaGetSymbolAddress((void**)&qx,  g_qkv_x);
    cudaGetSymbolAddress((void**)&qy,  g_qkv_y);
    cudaGetSymbolAddress((void**)&ax,  g_att_x);
    cudaGetSymbolAddress((void**)&ay,  g_att_y);
    cudaGetSymbolAddress((void**)&xh,  g_x_hi);     cudaGetSymbolAddress((void**)&xl,  g_x_lo);
    cudaGetSymbolAddress((void**)&yh,  g_y_hi);     cudaGetSymbolAddress((void**)&yl,  g_y_lo);
    cudaGetSymbolAddress((void**)&wqh, g_wqkv_hi);  cudaGetSymbolAddress((void**)&wql, g_wqkv_lo);
    cudaGetSymbolAddress((void**)&wph, g_wproj_hi); cudaGetSymbolAddress((void**)&wpl, g_wproj_lo);
    cudaGetSymbolAddress((void**)&axh, g_ax_hi);    cudaGetSymbolAddress((void**)&axl, g_ax_lo);
    cudaGetSymbolAddress((void**)&ayh, g_ay_hi);    cudaGetSymbolAddress((void**)&ayl, g_ay_lo);

    cudaFuncSetAttribute(gemm_mma<2>,
                         cudaFuncAttributeMaxDynamicSharedMemorySize, GEMM_SMEM);
    cudaFuncSetAttribute(gemm_mma<3>,
                         cudaFuncAttributeMaxDynamicSharedMemorySize, GEMM_SMEM);
    cudaFuncSetAttribute(attention_mma,
                         cudaFuncAttributeMaxDynamicSharedMemorySize, ATT_SMEM);

    // 0) fp32 -> fp16 limb pre-splits
    split_kernel<<<(M_ROWS*C_DIM/4 + 255)/256, 256>>>(x, xh, xl, M_ROWS*C_DIM/4);
    split_kernel<<<(M_ROWS*C_DIM/4 + 255)/256, 256>>>(y, yh, yl, M_ROWS*C_DIM/4);
    split_kernel<<<(QKV_DIM*C_DIM/4 + 255)/256, 256>>>(w_qkv, wqh, wql, QKV_DIM*C_DIM/4);
    split_kernel<<<(C_DIM*C_DIM/4 + 255)/256, 256>>>(w_proj, wph, wpl, C_DIM*C_DIM/4);

    // 1) QKV projections, 2-pass fp16; y-branch skips unused vy (N<2304)
    dim3 g1(QKV_DIM / 256, M_ROWS / 128, 2);
    gemm_mma<2><<<g1, 256, GEMM_SMEM>>>(xh, xl, yh, yl, wqh, wql, nullptr,
                                        qx, qy, M_ROWS, QKV_DIM, C_DIM, 2304);

    // 2) fused dual-softmax attention (fp16 2-pass)
    attention_mma<<<dim3(SEQ / 128, HEADS * 2, BATCH), 256, ATT_SMEM>>>();

    // 2b) split attention outputs to fp16 limbs for proj
    split_kernel<<<(M_ROWS*C_DIM/4 + 255)/256, 256>>>(ax, axh, axl, M_ROWS*C_DIM/4);
    split_kernel<<<(M_ROWS*C_DIM/4 + 255)/256, 256>>>(ay, ayh, ayl, M_ROWS*C_DIM/4);

    // 3) output projections + bias, 3-pass fp16 (keep precision margin)
    dim3 g2(C_DIM / 256, M_ROWS / 128, 2);
    gemm_mma<3><<<g2, 256, GEMM_SMEM>>>(axh, axl, ayh, ayl, wph, wpl, b_proj,
                                        out, out + (size_t)M_ROWS * C_DIM,
                                        M_ROWS, C_DIM, C_DIM, C_DIM);
}